// round 6
// baseline (speedup 1.0000x reference)
#include <cuda_runtime.h>
#include <cstdint>

#define NN 200000
#define CC 256
#define MM 50000
#define VCD 48   // 16 vector channels * 3 spatial dims

// Scratch accumulators (device globals; no allocation allowed in kernel_launch)
__device__ float g_s_sum[(size_t)MM * CC];   // 51.2 MB
__device__ float g_v_sum[(size_t)MM * VCD];  // 9.6 MB
__device__ float g_cnt[MM];
__device__ int   g_seg_is64;

// ============================ helpers ======================================
__device__ __forceinline__ uint32_t smem_u32(const void* p) {
    uint32_t a;
    asm("{ .reg .u64 t; cvta.to.shared.u64 t, %1; cvt.u32.u64 %0, t; }"
        : "=r"(a) : "l"(p));
    return a;
}
__device__ __forceinline__ float to_tf32(float x) {
    float r;
    asm("cvt.rna.tf32.f32 %0, %1;" : "=f"(r) : "f"(x));
    return r;
}
__device__ __forceinline__ void ldsm_x4(uint32_t* r, uint32_t addr) {
    asm volatile("ldmatrix.sync.aligned.m8n8.x4.shared.b16 {%0,%1,%2,%3}, [%4];"
        : "=r"(r[0]), "=r"(r[1]), "=r"(r[2]), "=r"(r[3]) : "r"(addr));
}
__device__ __forceinline__ void ldsm_x2(uint32_t* r, uint32_t addr) {
    asm volatile("ldmatrix.sync.aligned.m8n8.x2.shared.b16 {%0,%1}, [%2];"
        : "=r"(r[0]), "=r"(r[1]) : "r"(addr));
}
__device__ __forceinline__ void mma_tf32(float* c, const uint32_t* a, const uint32_t* b) {
    asm volatile(
        "mma.sync.aligned.m16n8k8.row.col.f32.tf32.tf32.f32 "
        "{%0,%1,%2,%3}, {%4,%5,%6,%7}, {%8,%9}, {%0,%1,%2,%3};"
        : "+f"(c[0]), "+f"(c[1]), "+f"(c[2]), "+f"(c[3])
        : "r"(a[0]), "r"(a[1]), "r"(a[2]), "r"(a[3]), "r"(b[0]), "r"(b[1]));
}
__device__ __forceinline__ void cp_async16(uint32_t saddr, const void* gaddr) {
    asm volatile("cp.async.ca.shared.global [%0], [%1], 16;"
                 :: "r"(saddr), "l"(gaddr) : "memory");
}
__device__ __forceinline__ void red_add_v4(float* addr, float4 val) {
    asm volatile("red.global.add.v4.f32 [%0], {%1,%2,%3,%4};"
                 :: "l"(addr), "f"(val.x), "f"(val.y), "f"(val.z), "f"(val.w)
                 : "memory");
}

// ---------------------------------------------------------------------------
// Probe the segment-index buffer's dtype (int64 vs int32).
// ---------------------------------------------------------------------------
__global__ void probe_seg_kernel(const int* __restrict__ seg32) {
    __shared__ int any_nonzero;
    if (threadIdx.x == 0) any_nonzero = 0;
    __syncthreads();
    for (int i = threadIdx.x; i < 1024; i += blockDim.x)
        if (seg32[2 * i + 1] != 0) any_nonzero = 1;
    __syncthreads();
    if (threadIdx.x == 0) g_seg_is64 = (any_nonzero == 0) ? 1 : 0;
}
__device__ __forceinline__ int load_seg(const void* seg, int n, int is64) {
    if (is64) return (int)((const long long*)seg)[n];
    return ((const int*)seg)[n];
}

// ---------------------------------------------------------------------------
__global__ void zero_kernel() {
    size_t i = blockIdx.x * (size_t)blockDim.x + threadIdx.x;
    size_t stride = (size_t)gridDim.x * blockDim.x;
    float4 z = make_float4(0.f, 0.f, 0.f, 0.f);
    float4* ps = (float4*)g_s_sum;
    size_t ns = (size_t)MM * CC / 4;
    for (size_t j = i; j < ns; j += stride) ps[j] = z;
    float4* pv = (float4*)g_v_sum;
    size_t nv = (size_t)MM * VCD / 4;
    for (size_t j = i; j < nv; j += stride) pv[j] = z;
    for (size_t j = i; j < MM; j += stride) g_cnt[j] = 0.f;
}

__global__ void scatter_s_kernel(const float* __restrict__ s,
                                 const void* __restrict__ seg) {
    long long i = blockIdx.x * (long long)blockDim.x + threadIdx.x;
    if (i >= (long long)NN * (CC / 4)) return;
    int n  = (int)(i >> 6);
    int c4 = (int)(i & 63);
    int m = load_seg(seg, n, g_seg_is64);
    if ((unsigned)m >= MM) return;
    float4 val = ((const float4*)s)[i];
    red_add_v4(&g_s_sum[(size_t)m * CC + c4 * 4], val);
}

__global__ void scatter_v_kernel(const float* __restrict__ v,
                                 const void* __restrict__ seg) {
    long long i = blockIdx.x * (long long)blockDim.x + threadIdx.x;
    if (i >= (long long)NN * (VCD / 4)) return;
    int n  = (int)(i / 12);
    int j4 = (int)(i % 12);
    int m = load_seg(seg, n, g_seg_is64);
    if ((unsigned)m >= MM) return;
    float4 val = ((const float4*)v)[i];
    red_add_v4(&g_v_sum[(size_t)m * VCD + j4 * 4], val);
    if (j4 == 0) atomicAdd(&g_cnt[m], 1.0f);
}

// ---------------------------------------------------------------------------
// tf32 mma.sync GEMM. A split hi/lo ONCE per element in the smem store path
// (R4 placement); mean division moved to epilogue; B double-buffered via
// cp.async; A globals register-prefetched under the MMA phase.
// BM=128, BN=128, BK=32. 8 warps 2(M)x4(N).
// ---------------------------------------------------------------------------
#define SMO_INVC 0
#define SMO_BS   512
#define SMO_AHI  1024
#define SMO_ALO  (1024 + 16384)
#define SMO_B    (1024 + 32768)       // 2 stages x 16KB
#define SMO_TOTAL (1024 + 65536)

__global__ void __launch_bounds__(256, 2)
gemm_s_mma(const float* __restrict__ Ws, const float* __restrict__ bs,
           float* __restrict__ out) {
    extern __shared__ char sm[];
    uint32_t sb = smem_u32(sm);
    int tid = threadIdx.x, wid = tid >> 5, lane = tid & 31;
    int wm = wid & 1, wn = wid >> 1;
    int m0 = blockIdx.y * 128, n0 = blockIdx.x * 128;

    float* invc = (float*)(sm + SMO_INVC);
    float* bssh = (float*)(sm + SMO_BS);
    if (tid < 128) {
        int gm = m0 + tid;
        float c = (gm < MM) ? g_cnt[gm] : 1.0f;
        invc[tid] = 1.0f / fmaxf(c, 1.0f);
        bssh[tid] = bs[n0 + tid];
    }

    // ---- per-thread load/store precompute (4 A chunks, 4 B chunks / BK)
    const float* gA[4]; const float* gB[4];
    uint32_t offAB[4];
#pragma unroll
    for (int i = 0; i < 4; i++) {
        int f = tid + 256 * i;
        int row = f >> 3, q = f & 7;
        int gm = m0 + row;
        gA[i] = g_s_sum + (size_t)(gm < MM ? gm : 0) * CC + q * 4;
        gB[i] = Ws + (size_t)(n0 + row) * CC + q * 4;
        offAB[i] = row * 128 + ((q ^ (row & 7)) << 4);
    }

    // ---- per-warp fragment addressing (identical to R4 known-good)
    int r8 = lane & 7;
    int halfA = (lane >> 3) & 1;
    int ksubA = lane >> 4;
    int ksubB = (lane >> 3) & 1;
    int lr = lane >> 2;
    uint32_t aRowOff[4]; int aRsw[4];
#pragma unroll
    for (int mi = 0; mi < 4; mi++) {
        int row = wm * 64 + mi * 16 + halfA * 8 + r8;
        aRowOff[mi] = row * 128;
        aRsw[mi] = row & 7;
    }
    uint32_t bRowOff[4];
#pragma unroll
    for (int ni = 0; ni < 4; ni++)
        bRowOff[ni] = (wn * 32 + ni * 8 + r8) * 128;

    float acc[4][4][4];
#pragma unroll
    for (int a = 0; a < 4; a++)
#pragma unroll
        for (int b = 0; b < 4; b++)
#pragma unroll
            for (int c = 0; c < 4; c++) acc[a][b][c] = 0.f;

    // ---- prologue: A(0) into regs, B(0) via cp.async into stage 0
    float4 aRegs[4];
#pragma unroll
    for (int i = 0; i < 4; i++) aRegs[i] = *(const float4*)(gA[i]);
    {
        uint32_t bb = sb + SMO_B;
#pragma unroll
        for (int i = 0; i < 4; i++) cp_async16(bb + offAB[i], gB[i]);
        asm volatile("cp.async.commit_group;" ::: "memory");
    }
    __syncthreads();   // also covers invc/bssh staging

    for (int ch = 0; ch < 8; ch++) {
        // ---- store A(ch): split hi/lo once per element
#pragma unroll
        for (int i = 0; i < 4; i++) {
            float4 a = aRegs[i];
            float4 hi, lo;
            hi.x = to_tf32(a.x); lo.x = a.x - hi.x;
            hi.y = to_tf32(a.y); lo.y = a.y - hi.y;
            hi.z = to_tf32(a.z); lo.z = a.z - hi.z;
            hi.w = to_tf32(a.w); lo.w = a.w - hi.w;
            *(float4*)(sm + SMO_AHI + offAB[i]) = hi;
            *(float4*)(sm + SMO_ALO + offAB[i]) = lo;
        }
        // ---- kick B(ch+1) into the other stage
        if (ch < 7) {
            uint32_t bb = sb + SMO_B + ((ch + 1) & 1) * 16384;
            int kt = (ch + 1) * 32;
#pragma unroll
            for (int i = 0; i < 4; i++) cp_async16(bb + offAB[i], gB[i] + kt);
            asm volatile("cp.async.commit_group;" ::: "memory");
            asm volatile("cp.async.wait_group 1;" ::: "memory");
        } else {
            asm volatile("cp.async.wait_group 0;" ::: "memory");
        }
        __syncthreads();

        // ---- prefetch A(ch+1) into regs; latency hidden by MMA phase below
        if (ch < 7) {
            int kt = (ch + 1) * 32;
#pragma unroll
            for (int i = 0; i < 4; i++) aRegs[i] = *(const float4*)(gA[i] + kt);
        }

        uint32_t bb = sb + SMO_B + (ch & 1) * 16384;
#pragma unroll
        for (int ks = 0; ks < 4; ks++) {
            int ks2 = ks * 2;
            uint32_t bf[4][2];
#pragma unroll
            for (int ni = 0; ni < 4; ni++) {
                ldsm_x2(bf[ni], bb + bRowOff[ni] + (((ks2 + ksubB) ^ r8) << 4));
                bf[ni][0] = __float_as_uint(to_tf32(__uint_as_float(bf[ni][0])));
                bf[ni][1] = __float_as_uint(to_tf32(__uint_as_float(bf[ni][1])));
            }
#pragma unroll
            for (int mi = 0; mi < 4; mi++) {
                uint32_t ah[4], al[4];
                uint32_t ca = ((uint32_t)((ks2 + ksubA) ^ aRsw[mi])) << 4;
                ldsm_x4(ah, sb + SMO_AHI + aRowOff[mi] + ca);
                ldsm_x4(al, sb + SMO_ALO + aRowOff[mi] + ca);
#pragma unroll
                for (int ni = 0; ni < 4; ni++) {
                    mma_tf32(acc[mi][ni], ah, bf[ni]);
                    mma_tf32(acc[mi][ni], al, bf[ni]);
                }
            }
        }
        __syncthreads();   // protect A smem before next chunk's stores
    }

    // ---- epilogue: scale by invc (mean), add bias
    int lc2 = 2 * (lane & 3);
#pragma unroll
    for (int mi = 0; mi < 4; mi++) {
        int rb = wm * 64 + mi * 16 + lr;
        float ic0 = invc[rb], ic1 = invc[rb + 8];
#pragma unroll
        for (int ni = 0; ni < 4; ni++) {
            int lcol = wn * 32 + ni * 8 + lc2;
            float b0 = bssh[lcol], b1 = bssh[lcol + 1];
            int row0 = m0 + rb;
            if (row0 < MM) {
                float2 o = make_float2(acc[mi][ni][0] * ic0 + b0,
                                       acc[mi][ni][1] * ic0 + b1);
                *(float2*)(out + (size_t)row0 * CC + n0 + lcol) = o;
            }
            int row1 = row0 + 8;
            if (row1 < MM) {
                float2 o = make_float2(acc[mi][ni][2] * ic1 + b0,
                                       acc[mi][ni][3] * ic1 + b1);
                *(float2*)(out + (size_t)row1 * CC + n0 + lcol) = o;
            }
        }
    }
}

// ---------------------------------------------------------------------------
__global__ void v_out_kernel(const float* __restrict__ Wv,
                             const float* __restrict__ bv,
                             float* __restrict__ out_v) {
    int i = blockIdx.x * blockDim.x + threadIdx.x;
    if (i >= MM * VCD) return;
    int m = i / 48;
    int r = i % 48;
    int o = r / 3, d = r % 3;
    float inv = 1.0f / fmaxf(g_cnt[m], 1.0f);
    const float* vm = g_v_sum + (size_t)m * 48;
    const float* w  = Wv + o * 16;
    float sum = 0.f;
#pragma unroll
    for (int c = 0; c < 16; c++) sum += w[c] * vm[c * 3 + d];
    out_v[i] = sum * inv + bv[o];
}

// ---------------------------------------------------------------------------
extern "C" void kernel_launch(void* const* d_in, const int* in_sizes, int n_in,
                              void* d_out, int out_size) {
    const float* s   = (const float*)d_in[0];
    const float* v   = (const float*)d_in[1];
    const void*  seg = d_in[2];
    const float* Ws  = (const float*)d_in[3];
    const float* bs  = (const float*)d_in[4];
    const float* Wv  = (const float*)d_in[5];
    const float* bv  = (const float*)d_in[6];
    float* out_s = (float*)d_out;
    float* out_v = out_s + (size_t)MM * CC;

    static int smem_set = 0;
    if (!smem_set) {
        cudaFuncSetAttribute(gemm_s_mma,
                             cudaFuncAttributeMaxDynamicSharedMemorySize, SMO_TOTAL);
        smem_set = 1;
    }

    probe_seg_kernel<<<1, 256>>>((const int*)seg);
    zero_kernel<<<2048, 256>>>();

    long long s_threads = (long long)NN * (CC / 4);
    scatter_s_kernel<<<(int)((s_threads + 255) / 256), 256>>>(s, seg);

    long long v_threads = (long long)NN * (VCD / 4);
    scatter_v_kernel<<<(int)((v_threads + 255) / 256), 256>>>(v, seg);

    dim3 gg(CC / 128, (MM + 127) / 128);
    gemm_s_mma<<<gg, 256, SMO_TOTAL>>>(Ws, bs, out_s);

    v_out_kernel<<<(MM * VCD + 255) / 256, 256>>>(Wv, bv, out_v);
}

// round 7
// speedup vs baseline: 1.2789x; 1.2789x over previous
#include <cuda_runtime.h>
#include <cstdint>

#define NN 200000
#define CC 256
#define MM 50000
#define VCD 48   // 16 vector channels * 3 spatial dims

// Scratch accumulators (device globals; no allocation allowed in kernel_launch)
__device__ float g_s_sum[(size_t)MM * CC];   // 51.2 MB
__device__ float g_v_sum[(size_t)MM * VCD];  // 9.6 MB
__device__ float g_cnt[MM];
__device__ int   g_seg_is64;

// ============================ helpers ======================================
__device__ __forceinline__ uint32_t smem_u32(const void* p) {
    uint32_t a;
    asm("{ .reg .u64 t; cvta.to.shared.u64 t, %1; cvt.u32.u64 %0, t; }"
        : "=r"(a) : "l"(p));
    return a;
}
__device__ __forceinline__ float to_tf32(float x) {
    float r;
    asm("cvt.rna.tf32.f32 %0, %1;" : "=f"(r) : "f"(x));
    return r;
}
__device__ __forceinline__ void ldsm_x4(uint32_t* r, uint32_t addr) {
    asm volatile("ldmatrix.sync.aligned.m8n8.x4.shared.b16 {%0,%1,%2,%3}, [%4];"
        : "=r"(r[0]), "=r"(r[1]), "=r"(r[2]), "=r"(r[3]) : "r"(addr));
}
__device__ __forceinline__ void ldsm_x2(uint32_t* r, uint32_t addr) {
    asm volatile("ldmatrix.sync.aligned.m8n8.x2.shared.b16 {%0,%1}, [%2];"
        : "=r"(r[0]), "=r"(r[1]) : "r"(addr));
}
__device__ __forceinline__ void mma_tf32(float* c, const uint32_t* a, const uint32_t* b) {
    asm volatile(
        "mma.sync.aligned.m16n8k8.row.col.f32.tf32.tf32.f32 "
        "{%0,%1,%2,%3}, {%4,%5,%6,%7}, {%8,%9}, {%0,%1,%2,%3};"
        : "+f"(c[0]), "+f"(c[1]), "+f"(c[2]), "+f"(c[3])
        : "r"(a[0]), "r"(a[1]), "r"(a[2]), "r"(a[3]), "r"(b[0]), "r"(b[1]));
}
__device__ __forceinline__ void red_add_v4(float* addr, float4 val) {
    asm volatile("red.global.add.v4.f32 [%0], {%1,%2,%3,%4};"
                 :: "l"(addr), "f"(val.x), "f"(val.y), "f"(val.z), "f"(val.w)
                 : "memory");
}

// ---------------------------------------------------------------------------
// Probe the segment-index buffer's dtype (int64 vs int32).
// ---------------------------------------------------------------------------
__global__ void probe_seg_kernel(const int* __restrict__ seg32) {
    __shared__ int any_nonzero;
    if (threadIdx.x == 0) any_nonzero = 0;
    __syncthreads();
    for (int i = threadIdx.x; i < 1024; i += blockDim.x)
        if (seg32[2 * i + 1] != 0) any_nonzero = 1;
    __syncthreads();
    if (threadIdx.x == 0) g_seg_is64 = (any_nonzero == 0) ? 1 : 0;
}
__device__ __forceinline__ int load_seg(const void* seg, int n, int is64) {
    if (is64) return (int)((const long long*)seg)[n];
    return ((const int*)seg)[n];
}

// ---------------------------------------------------------------------------
__global__ void zero_kernel() {
    size_t i = blockIdx.x * (size_t)blockDim.x + threadIdx.x;
    size_t stride = (size_t)gridDim.x * blockDim.x;
    float4 z = make_float4(0.f, 0.f, 0.f, 0.f);
    float4* ps = (float4*)g_s_sum;
    size_t ns = (size_t)MM * CC / 4;
    for (size_t j = i; j < ns; j += stride) ps[j] = z;
    float4* pv = (float4*)g_v_sum;
    size_t nv = (size_t)MM * VCD / 4;
    for (size_t j = i; j < nv; j += stride) pv[j] = z;
    for (size_t j = i; j < MM; j += stride) g_cnt[j] = 0.f;
}

__global__ void scatter_s_kernel(const float* __restrict__ s,
                                 const void* __restrict__ seg) {
    long long i = blockIdx.x * (long long)blockDim.x + threadIdx.x;
    if (i >= (long long)NN * (CC / 4)) return;
    int n  = (int)(i >> 6);
    int c4 = (int)(i & 63);
    int m = load_seg(seg, n, g_seg_is64);
    if ((unsigned)m >= MM) return;
    float4 val = ((const float4*)s)[i];
    red_add_v4(&g_s_sum[(size_t)m * CC + c4 * 4], val);
}

__global__ void scatter_v_kernel(const float* __restrict__ v,
                                 const void* __restrict__ seg) {
    long long i = blockIdx.x * (long long)blockDim.x + threadIdx.x;
    if (i >= (long long)NN * (VCD / 4)) return;
    int n  = (int)(i / 12);
    int j4 = (int)(i % 12);
    int m = load_seg(seg, n, g_seg_is64);
    if ((unsigned)m >= MM) return;
    float4 val = ((const float4*)v)[i];
    red_add_v4(&g_v_sum[(size_t)m * VCD + j4 * 4], val);
    if (j4 == 0) atomicAdd(&g_cnt[m], 1.0f);
}

// ---------------------------------------------------------------------------
// Single-pass tf32 mma.sync GEMM (R4 structure, lo-term dropped).
// BM=128, BN=128, BK=32. 8 warps: 2(M)x4(N); each warp 64x32 via 4x4 m16n8k8
// fragments. SMEM tiles [row][32 floats], 16B chunks XOR-swizzled (q ^ row&7).
// Mean fused into A load; A and B rounded to tf32 (rel err ~3e-4).
// ---------------------------------------------------------------------------
#define SMO_INVC 0
#define SMO_BS   512
#define SMO_A    1024
#define SMO_B    (1024 + 16384)
#define SMO_TOTAL (1024 + 32768)

__global__ void __launch_bounds__(256, 3)
gemm_s_mma(const float* __restrict__ Ws, const float* __restrict__ bs,
           float* __restrict__ out) {
    extern __shared__ char sm[];
    uint32_t sb = smem_u32(sm);
    int tid = threadIdx.x, wid = tid >> 5, lane = tid & 31;
    int wm = wid & 1, wn = wid >> 1;
    int m0 = blockIdx.y * 128, n0 = blockIdx.x * 128;

    float* invc = (float*)(sm + SMO_INVC);
    float* bssh = (float*)(sm + SMO_BS);
    if (tid < 128) {
        int gm = m0 + tid;
        float c = (gm < MM) ? g_cnt[gm] : 1.0f;
        invc[tid] = 1.0f / fmaxf(c, 1.0f);
        bssh[tid] = bs[n0 + tid];
    }
    __syncthreads();

    float acc[4][4][4];
#pragma unroll
    for (int a = 0; a < 4; a++)
#pragma unroll
        for (int b = 0; b < 4; b++)
#pragma unroll
            for (int c = 0; c < 4; c++) acc[a][b][c] = 0.f;

    // per-lane ldmatrix row precompute
    int r8 = lane & 7;
    int halfA = (lane >> 3) & 1;
    int ksubA = lane >> 4;          // 0,0,1,1 per 8-lane group
    int ksubB = (lane >> 3) & 1;
    uint32_t aRowOff[4]; int aRsw[4];
#pragma unroll
    for (int mi = 0; mi < 4; mi++) {
        int row = wm * 64 + mi * 16 + halfA * 8 + r8;
        aRowOff[mi] = row * 128;
        aRsw[mi] = row & 7;
    }
    uint32_t bRowOff[4];
#pragma unroll
    for (int ni = 0; ni < 4; ni++)
        bRowOff[ni] = (wn * 32 + ni * 8 + r8) * 128;

    for (int ch = 0; ch < 8; ch++) {
        int kt = ch * 32;
        // ---- A chunk: 128x32, scale by invc, round to tf32
#pragma unroll
        for (int i = 0; i < 4; i++) {
            int f = tid + 256 * i;
            int row = f >> 3, q = f & 7;
            int gm = m0 + row;
            float4 a = (gm < MM)
                ? *(const float4*)(g_s_sum + (size_t)gm * CC + kt + q * 4)
                : make_float4(0.f, 0.f, 0.f, 0.f);
            float sc = invc[row];
            a.x = to_tf32(a.x * sc); a.y = to_tf32(a.y * sc);
            a.z = to_tf32(a.z * sc); a.w = to_tf32(a.w * sc);
            uint32_t off = row * 128 + ((q ^ (row & 7)) << 4);
            *(float4*)(sm + SMO_A + off) = a;
        }
        // ---- B chunk: 128 out-channels x 32 k (rounded to tf32)
#pragma unroll
        for (int i = 0; i < 4; i++) {
            int f = tid + 256 * i;
            int row = f >> 3, q = f & 7;
            float4 b = *(const float4*)(Ws + (size_t)(n0 + row) * CC + kt + q * 4);
            b.x = to_tf32(b.x); b.y = to_tf32(b.y);
            b.z = to_tf32(b.z); b.w = to_tf32(b.w);
            uint32_t off = row * 128 + ((q ^ (row & 7)) << 4);
            *(float4*)(sm + SMO_B + off) = b;
        }
        __syncthreads();

#pragma unroll
        for (int ks = 0; ks < 4; ks++) {
            int ks2 = ks * 2;
            uint32_t bf[4][2];
#pragma unroll
            for (int ni = 0; ni < 4; ni++)
                ldsm_x2(bf[ni], sb + SMO_B + bRowOff[ni] + (((ks2 + ksubB) ^ r8) << 4));
#pragma unroll
            for (int mi = 0; mi < 4; mi++) {
                uint32_t ah[4];
                uint32_t ca = ((uint32_t)((ks2 + ksubA) ^ aRsw[mi])) << 4;
                ldsm_x4(ah, sb + SMO_A + aRowOff[mi] + ca);
#pragma unroll
                for (int ni = 0; ni < 4; ni++)
                    mma_tf32(acc[mi][ni], ah, bf[ni]);
            }
        }
        __syncthreads();
    }

    // ---- epilogue
    int lr = lane >> 2, lc2 = 2 * (lane & 3);
#pragma unroll
    for (int mi = 0; mi < 4; mi++) {
#pragma unroll
        for (int ni = 0; ni < 4; ni++) {
            int lcol = wn * 32 + ni * 8 + lc2;
            float b0 = bssh[lcol], b1 = bssh[lcol + 1];
            int row0 = m0 + wm * 64 + mi * 16 + lr;
            if (row0 < MM) {
                float2 o = make_float2(acc[mi][ni][0] + b0, acc[mi][ni][1] + b1);
                *(float2*)(out + (size_t)row0 * CC + n0 + lcol) = o;
            }
            int row1 = row0 + 8;
            if (row1 < MM) {
                float2 o = make_float2(acc[mi][ni][2] + b0, acc[mi][ni][3] + b1);
                *(float2*)(out + (size_t)row1 * CC + n0 + lcol) = o;
            }
        }
    }
}

// ---------------------------------------------------------------------------
__global__ void v_out_kernel(const float* __restrict__ Wv,
                             const float* __restrict__ bv,
                             float* __restrict__ out_v) {
    int i = blockIdx.x * blockDim.x + threadIdx.x;
    if (i >= MM * VCD) return;
    int m = i / 48;
    int r = i % 48;
    int o = r / 3, d = r % 3;
    float inv = 1.0f / fmaxf(g_cnt[m], 1.0f);
    const float* vm = g_v_sum + (size_t)m * 48;
    const float* w  = Wv + o * 16;
    float sum = 0.f;
#pragma unroll
    for (int c = 0; c < 16; c++) sum += w[c] * vm[c * 3 + d];
    out_v[i] = sum * inv + bv[o];
}

// ---------------------------------------------------------------------------
extern "C" void kernel_launch(void* const* d_in, const int* in_sizes, int n_in,
                              void* d_out, int out_size) {
    const float* s   = (const float*)d_in[0];
    const float* v   = (const float*)d_in[1];
    const void*  seg = d_in[2];
    const float* Ws  = (const float*)d_in[3];
    const float* bs  = (const float*)d_in[4];
    const float* Wv  = (const float*)d_in[5];
    const float* bv  = (const float*)d_in[6];
    float* out_s = (float*)d_out;
    float* out_v = out_s + (size_t)MM * CC;

    static int smem_set = 0;
    if (!smem_set) {
        cudaFuncSetAttribute(gemm_s_mma,
                             cudaFuncAttributeMaxDynamicSharedMemorySize, SMO_TOTAL);
        smem_set = 1;
    }

    probe_seg_kernel<<<1, 256>>>((const int*)seg);
    zero_kernel<<<2048, 256>>>();

    long long s_threads = (long long)NN * (CC / 4);
    scatter_s_kernel<<<(int)((s_threads + 255) / 256), 256>>>(s, seg);

    long long v_threads = (long long)NN * (VCD / 4);
    scatter_v_kernel<<<(int)((v_threads + 255) / 256), 256>>>(v, seg);

    dim3 gg(CC / 128, (MM + 127) / 128);
    gemm_s_mma<<<gg, 256, SMO_TOTAL>>>(Ws, bs, out_s);

    v_out_kernel<<<(MM * VCD + 255) / 256, 256>>>(Wv, bv, out_v);
}

// round 8
// speedup vs baseline: 1.5293x; 1.1958x over previous
#include <cuda_runtime.h>
#include <cstdint>

#define NN 200000
#define CC 256
#define MM 50000
#define VCD 48   // 16 vector channels * 3 spatial dims

// Scratch accumulators (device globals; no allocation allowed in kernel_launch)
__device__ float g_s_sum[(size_t)MM * CC];   // 51.2 MB
__device__ float g_v_sum[(size_t)MM * VCD];  // 9.6 MB
__device__ float g_cnt[MM];
__device__ int   g_seg_is64;

// ============================ helpers ======================================
__device__ __forceinline__ uint32_t smem_u32(const void* p) {
    uint32_t a;
    asm("{ .reg .u64 t; cvta.to.shared.u64 t, %1; cvt.u32.u64 %0, t; }"
        : "=r"(a) : "l"(p));
    return a;
}
__device__ __forceinline__ float to_tf32(float x) {
    float r;
    asm("cvt.rna.tf32.f32 %0, %1;" : "=f"(r) : "f"(x));
    return r;
}
__device__ __forceinline__ void ldsm_x4(uint32_t* r, uint32_t addr) {
    asm volatile("ldmatrix.sync.aligned.m8n8.x4.shared.b16 {%0,%1,%2,%3}, [%4];"
        : "=r"(r[0]), "=r"(r[1]), "=r"(r[2]), "=r"(r[3]) : "r"(addr));
}
__device__ __forceinline__ void ldsm_x2(uint32_t* r, uint32_t addr) {
    asm volatile("ldmatrix.sync.aligned.m8n8.x2.shared.b16 {%0,%1}, [%2];"
        : "=r"(r[0]), "=r"(r[1]) : "r"(addr));
}
__device__ __forceinline__ void mma_tf32(float* c, const uint32_t* a, const uint32_t* b) {
    asm volatile(
        "mma.sync.aligned.m16n8k8.row.col.f32.tf32.tf32.f32 "
        "{%0,%1,%2,%3}, {%4,%5,%6,%7}, {%8,%9}, {%0,%1,%2,%3};"
        : "+f"(c[0]), "+f"(c[1]), "+f"(c[2]), "+f"(c[3])
        : "r"(a[0]), "r"(a[1]), "r"(a[2]), "r"(a[3]), "r"(b[0]), "r"(b[1]));
}
__device__ __forceinline__ void red_add_v4(float* addr, float4 val) {
    asm volatile("red.global.add.v4.f32 [%0], {%1,%2,%3,%4};"
                 :: "l"(addr), "f"(val.x), "f"(val.y), "f"(val.z), "f"(val.w)
                 : "memory");
}

// ---------------------------------------------------------------------------
// Probe the segment-index buffer's dtype (int64 vs int32).
// ---------------------------------------------------------------------------
__global__ void probe_seg_kernel(const int* __restrict__ seg32) {
    __shared__ int any_nonzero;
    if (threadIdx.x == 0) any_nonzero = 0;
    __syncthreads();
    for (int i = threadIdx.x; i < 1024; i += blockDim.x)
        if (seg32[2 * i + 1] != 0) any_nonzero = 1;
    __syncthreads();
    if (threadIdx.x == 0) g_seg_is64 = (any_nonzero == 0) ? 1 : 0;
}
__device__ __forceinline__ int load_seg(const void* seg, int n, int is64) {
    if (is64) return (int)((const long long*)seg)[n];
    return ((const int*)seg)[n];
}

// ---------------------------------------------------------------------------
__global__ void zero_kernel() {
    size_t i = blockIdx.x * (size_t)blockDim.x + threadIdx.x;
    size_t stride = (size_t)gridDim.x * blockDim.x;
    float4 z = make_float4(0.f, 0.f, 0.f, 0.f);
    float4* ps = (float4*)g_s_sum;
    size_t ns = (size_t)MM * CC / 4;
    for (size_t j = i; j < ns; j += stride) ps[j] = z;
    float4* pv = (float4*)g_v_sum;
    size_t nv = (size_t)MM * VCD / 4;
    for (size_t j = i; j < nv; j += stride) pv[j] = z;
    for (size_t j = i; j < MM; j += stride) g_cnt[j] = 0.f;
}

// ---------------------------------------------------------------------------
// Scatter-add s: one thread per (node, 8-channel chunk): 2 independent
// float4 loads + 2 v4 reductions -> MLP=2 per thread.
// ---------------------------------------------------------------------------
__global__ void scatter_s_kernel(const float* __restrict__ s,
                                 const void* __restrict__ seg) {
    long long i = blockIdx.x * (long long)blockDim.x + threadIdx.x;
    if (i >= (long long)NN * (CC / 8)) return;
    int n  = (int)(i >> 5);   // CC/8 == 32 chunks per node
    int c8 = (int)(i & 31);
    int m = load_seg(seg, n, g_seg_is64);
    float4 v0 = ((const float4*)s)[2 * i];
    float4 v1 = ((const float4*)s)[2 * i + 1];
    if ((unsigned)m >= MM) return;
    float* dst = &g_s_sum[(size_t)m * CC + c8 * 8];
    red_add_v4(dst, v0);
    red_add_v4(dst + 4, v1);
}

// ---------------------------------------------------------------------------
// Scatter-add v (+ counts): one thread per (node, 8-float chunk of 48):
// 2 loads + 2 reductions, MLP=2.
// ---------------------------------------------------------------------------
__global__ void scatter_v_kernel(const float* __restrict__ v,
                                 const void* __restrict__ seg) {
    long long i = blockIdx.x * (long long)blockDim.x + threadIdx.x;
    if (i >= (long long)NN * (VCD / 8)) return;
    int n  = (int)(i / 6);
    int j8 = (int)(i % 6);
    int m = load_seg(seg, n, g_seg_is64);
    float4 v0 = ((const float4*)v)[2 * i];
    float4 v1 = ((const float4*)v)[2 * i + 1];
    if ((unsigned)m >= MM) return;
    float* dst = &g_v_sum[(size_t)m * VCD + j8 * 8];
    red_add_v4(dst, v0);
    red_add_v4(dst + 4, v1);
    if (j8 == 0) atomicAdd(&g_cnt[m], 1.0f);
}

// ---------------------------------------------------------------------------
// Single-pass tf32 mma.sync GEMM (R4 structure, lo-term dropped, occ=2).
// BM=128, BN=128, BK=32. 8 warps 2(M)x4(N); each warp 64x32 via 4x4 m16n8k8.
// SMEM tiles [row][32 floats], 16B chunks XOR-swizzled (q ^ row&7).
// Mean fused into A load; A and B rounded to tf32 (rel err ~3e-4).
// ---------------------------------------------------------------------------
#define SMO_INVC 0
#define SMO_BS   512
#define SMO_A    1024
#define SMO_B    (1024 + 16384)
#define SMO_TOTAL (1024 + 32768)

__global__ void __launch_bounds__(256, 2)
gemm_s_mma(const float* __restrict__ Ws, const float* __restrict__ bs,
           float* __restrict__ out) {
    extern __shared__ char sm[];
    uint32_t sb = smem_u32(sm);
    int tid = threadIdx.x, wid = tid >> 5, lane = tid & 31;
    int wm = wid & 1, wn = wid >> 1;
    int m0 = blockIdx.y * 128, n0 = blockIdx.x * 128;

    float* invc = (float*)(sm + SMO_INVC);
    float* bssh = (float*)(sm + SMO_BS);
    if (tid < 128) {
        int gm = m0 + tid;
        float c = (gm < MM) ? g_cnt[gm] : 1.0f;
        invc[tid] = 1.0f / fmaxf(c, 1.0f);
        bssh[tid] = bs[n0 + tid];
    }
    __syncthreads();

    float acc[4][4][4];
#pragma unroll
    for (int a = 0; a < 4; a++)
#pragma unroll
        for (int b = 0; b < 4; b++)
#pragma unroll
            for (int c = 0; c < 4; c++) acc[a][b][c] = 0.f;

    // per-lane ldmatrix row precompute
    int r8 = lane & 7;
    int halfA = (lane >> 3) & 1;
    int ksubA = lane >> 4;          // 0,0,1,1 per 8-lane group
    int ksubB = (lane >> 3) & 1;
    uint32_t aRowOff[4]; int aRsw[4];
#pragma unroll
    for (int mi = 0; mi < 4; mi++) {
        int row = wm * 64 + mi * 16 + halfA * 8 + r8;
        aRowOff[mi] = row * 128;
        aRsw[mi] = row & 7;
    }
    uint32_t bRowOff[4];
#pragma unroll
    for (int ni = 0; ni < 4; ni++)
        bRowOff[ni] = (wn * 32 + ni * 8 + r8) * 128;

    for (int ch = 0; ch < 8; ch++) {
        int kt = ch * 32;
        // ---- A chunk: 128x32, scale by invc, round to tf32
#pragma unroll
        for (int i = 0; i < 4; i++) {
            int f = tid + 256 * i;
            int row = f >> 3, q = f & 7;
            int gm = m0 + row;
            float4 a = (gm < MM)
                ? *(const float4*)(g_s_sum + (size_t)gm * CC + kt + q * 4)
                : make_float4(0.f, 0.f, 0.f, 0.f);
            float sc = invc[row];
            a.x = to_tf32(a.x * sc); a.y = to_tf32(a.y * sc);
            a.z = to_tf32(a.z * sc); a.w = to_tf32(a.w * sc);
            uint32_t off = row * 128 + ((q ^ (row & 7)) << 4);
            *(float4*)(sm + SMO_A + off) = a;
        }
        // ---- B chunk: 128 out-channels x 32 k (rounded to tf32)
#pragma unroll
        for (int i = 0; i < 4; i++) {
            int f = tid + 256 * i;
            int row = f >> 3, q = f & 7;
            float4 b = *(const float4*)(Ws + (size_t)(n0 + row) * CC + kt + q * 4);
            b.x = to_tf32(b.x); b.y = to_tf32(b.y);
            b.z = to_tf32(b.z); b.w = to_tf32(b.w);
            uint32_t off = row * 128 + ((q ^ (row & 7)) << 4);
            *(float4*)(sm + SMO_B + off) = b;
        }
        __syncthreads();

#pragma unroll
        for (int ks = 0; ks < 4; ks++) {
            int ks2 = ks * 2;
            uint32_t bf[4][2];
#pragma unroll
            for (int ni = 0; ni < 4; ni++)
                ldsm_x2(bf[ni], sb + SMO_B + bRowOff[ni] + (((ks2 + ksubB) ^ r8) << 4));
#pragma unroll
            for (int mi = 0; mi < 4; mi++) {
                uint32_t ah[4];
                uint32_t ca = ((uint32_t)((ks2 + ksubA) ^ aRsw[mi])) << 4;
                ldsm_x4(ah, sb + SMO_A + aRowOff[mi] + ca);
#pragma unroll
                for (int ni = 0; ni < 4; ni++)
                    mma_tf32(acc[mi][ni], ah, bf[ni]);
            }
        }
        __syncthreads();
    }

    // ---- epilogue
    int lr = lane >> 2, lc2 = 2 * (lane & 3);
#pragma unroll
    for (int mi = 0; mi < 4; mi++) {
#pragma unroll
        for (int ni = 0; ni < 4; ni++) {
            int lcol = wn * 32 + ni * 8 + lc2;
            float b0 = bssh[lcol], b1 = bssh[lcol + 1];
            int row0 = m0 + wm * 64 + mi * 16 + lr;
            if (row0 < MM) {
                float2 o = make_float2(acc[mi][ni][0] + b0, acc[mi][ni][1] + b1);
                *(float2*)(out + (size_t)row0 * CC + n0 + lcol) = o;
            }
            int row1 = row0 + 8;
            if (row1 < MM) {
                float2 o = make_float2(acc[mi][ni][2] + b0, acc[mi][ni][3] + b1);
                *(float2*)(out + (size_t)row1 * CC + n0 + lcol) = o;
            }
        }
    }
}

// ---------------------------------------------------------------------------
__global__ void v_out_kernel(const float* __restrict__ Wv,
                             const float* __restrict__ bv,
                             float* __restrict__ out_v) {
    int i = blockIdx.x * blockDim.x + threadIdx.x;
    if (i >= MM * VCD) return;
    int m = i / 48;
    int r = i % 48;
    int o = r / 3, d = r % 3;
    float inv = 1.0f / fmaxf(g_cnt[m], 1.0f);
    const float* vm = g_v_sum + (size_t)m * 48;
    const float* w  = Wv + o * 16;
    float sum = 0.f;
#pragma unroll
    for (int c = 0; c < 16; c++) sum += w[c] * vm[c * 3 + d];
    out_v[i] = sum * inv + bv[o];
}

// ---------------------------------------------------------------------------
extern "C" void kernel_launch(void* const* d_in, const int* in_sizes, int n_in,
                              void* d_out, int out_size) {
    const float* s   = (const float*)d_in[0];
    const float* v   = (const float*)d_in[1];
    const void*  seg = d_in[2];
    const float* Ws  = (const float*)d_in[3];
    const float* bs  = (const float*)d_in[4];
    const float* Wv  = (const float*)d_in[5];
    const float* bv  = (const float*)d_in[6];
    float* out_s = (float*)d_out;
    float* out_v = out_s + (size_t)MM * CC;

    static int smem_set = 0;
    if (!smem_set) {
        cudaFuncSetAttribute(gemm_s_mma,
                             cudaFuncAttributeMaxDynamicSharedMemorySize, SMO_TOTAL);
        smem_set = 1;
    }

    probe_seg_kernel<<<1, 256>>>((const int*)seg);
    zero_kernel<<<2048, 256>>>();

    long long s_threads = (long long)NN * (CC / 8);
    scatter_s_kernel<<<(int)((s_threads + 255) / 256), 256>>>(s, seg);

    long long v_threads = (long long)NN * (VCD / 8);
    scatter_v_kernel<<<(int)((v_threads + 255) / 256), 256>>>(v, seg);

    dim3 gg(CC / 128, (MM + 127) / 128);
    gemm_s_mma<<<gg, 256, SMO_TOTAL>>>(Ws, bs, out_s);

    v_out_kernel<<<(MM * VCD + 255) / 256, 256>>>(Wv, bv, out_v);
}

// round 9
// speedup vs baseline: 1.7183x; 1.1236x over previous
#include <cuda_runtime.h>
#include <cstdint>

#define NN 200000
#define CC 256
#define MM 50000
#define VCD 48   // 16 vector channels * 3 spatial dims
#define NB 98    // scan blocks: ceil(MM / 512)

// Scratch (device globals; no allocation allowed in kernel_launch)
__device__ float g_s_mean[(size_t)MM * CC];   // 51.2 MB
__device__ float g_v_mean[(size_t)MM * VCD];  // 9.6 MB
__device__ int   g_hist[MM];
__device__ int   g_bsum[NB];
__device__ int   g_off[MM + 1];
__device__ int   g_fill[MM];
__device__ int   g_perm[NN];
__device__ int   g_seg_is64;

// ============================ helpers ======================================
__device__ __forceinline__ uint32_t smem_u32(const void* p) {
    uint32_t a;
    asm("{ .reg .u64 t; cvta.to.shared.u64 t, %1; cvt.u32.u64 %0, t; }"
        : "=r"(a) : "l"(p));
    return a;
}
__device__ __forceinline__ float to_tf32(float x) {
    float r;
    asm("cvt.rna.tf32.f32 %0, %1;" : "=f"(r) : "f"(x));
    return r;
}
__device__ __forceinline__ void ldsm_x4(uint32_t* r, uint32_t addr) {
    asm volatile("ldmatrix.sync.aligned.m8n8.x4.shared.b16 {%0,%1,%2,%3}, [%4];"
        : "=r"(r[0]), "=r"(r[1]), "=r"(r[2]), "=r"(r[3]) : "r"(addr));
}
__device__ __forceinline__ void ldsm_x2(uint32_t* r, uint32_t addr) {
    asm volatile("ldmatrix.sync.aligned.m8n8.x2.shared.b16 {%0,%1}, [%2];"
        : "=r"(r[0]), "=r"(r[1]) : "r"(addr));
}
__device__ __forceinline__ void mma_tf32(float* c, const uint32_t* a, const uint32_t* b) {
    asm volatile(
        "mma.sync.aligned.m16n8k8.row.col.f32.tf32.tf32.f32 "
        "{%0,%1,%2,%3}, {%4,%5,%6,%7}, {%8,%9}, {%0,%1,%2,%3};"
        : "+f"(c[0]), "+f"(c[1]), "+f"(c[2]), "+f"(c[3])
        : "r"(a[0]), "r"(a[1]), "r"(a[2]), "r"(a[3]), "r"(b[0]), "r"(b[1]));
}
__device__ __forceinline__ void add4(float4& a, const float4 b) {
    a.x += b.x; a.y += b.y; a.z += b.z; a.w += b.w;
}

// ---------------------------------------------------------------------------
// Probe the segment-index buffer's dtype (int64 vs int32).
// ---------------------------------------------------------------------------
__global__ void probe_seg_kernel(const int* __restrict__ seg32) {
    __shared__ int any_nonzero;
    if (threadIdx.x == 0) any_nonzero = 0;
    __syncthreads();
    for (int i = threadIdx.x; i < 1024; i += blockDim.x)
        if (seg32[2 * i + 1] != 0) any_nonzero = 1;
    __syncthreads();
    if (threadIdx.x == 0) g_seg_is64 = (any_nonzero == 0) ? 1 : 0;
}
__device__ __forceinline__ int load_seg(const void* seg, int n, int is64) {
    if (is64) return (int)((const long long*)seg)[n];
    return ((const int*)seg)[n];
}

// ======================= counting sort build ===============================
__global__ void zero_hist_kernel() {
    int i = blockIdx.x * blockDim.x + threadIdx.x;
    if (i < MM) g_hist[i] = 0;
}

__global__ void hist_kernel(const void* __restrict__ seg) {
    int n = blockIdx.x * blockDim.x + threadIdx.x;
    if (n >= NN) return;
    int m = load_seg(seg, n, g_seg_is64);
    if ((unsigned)m < MM) atomicAdd(&g_hist[m], 1);
}

// scan_a: per-block (512 elems) sum
__global__ void scan_a_kernel() {
    __shared__ int red[256];
    int b = blockIdx.x, t = threadIdx.x;
    int i0 = b * 512 + t, i1 = i0 + 256;
    int c = (i0 < MM ? g_hist[i0] : 0) + (i1 < MM ? g_hist[i1] : 0);
    red[t] = c;
    __syncthreads();
    for (int s = 128; s > 0; s >>= 1) {
        if (t < s) red[t] += red[t + s];
        __syncthreads();
    }
    if (t == 0) g_bsum[b] = red[0];
}

// scan_b: exclusive scan of NB block sums (in smem), write total to g_off[MM]
__global__ void scan_b_kernel() {
    __shared__ int sh[NB];
    int t = threadIdx.x;
    for (int i = t; i < NB; i += blockDim.x) sh[i] = g_bsum[i];
    __syncthreads();
    if (t == 0) {
        int run = 0;
        for (int i = 0; i < NB; i++) { int tmp = sh[i]; sh[i] = run; run += tmp; }
        g_off[MM] = run;
    }
    __syncthreads();
    for (int i = t; i < NB; i += blockDim.x) g_bsum[i] = sh[i];
}

// scan_c: per-block exclusive scan over its 512 counts + block base -> g_off, g_fill
__global__ void scan_c_kernel() {
    __shared__ int buf0[256], buf1[256];
    int b = blockIdx.x, t = threadIdx.x;
    int i0 = b * 512 + 2 * t, i1 = i0 + 1;
    int c0 = (i0 < MM) ? g_hist[i0] : 0;
    int c1 = (i1 < MM) ? g_hist[i1] : 0;
    int psum = c0 + c1;
    // inclusive Hillis-Steele over 256 pair-sums (ping-pong)
    buf0[t] = psum;
    __syncthreads();
    int* src = buf0; int* dst = buf1;
#pragma unroll
    for (int off = 1; off < 256; off <<= 1) {
        int val = src[t];
        if (t >= off) val += src[t - off];
        dst[t] = val;
        __syncthreads();
        int* tmp = src; src = dst; dst = tmp;
    }
    int excl = src[t] - psum;
    int base = g_bsum[b] + excl;
    if (i0 < MM) { g_off[i0] = base;      g_fill[i0] = base; }
    if (i1 < MM) { g_off[i1] = base + c0; g_fill[i1] = base + c0; }
}

__global__ void perm_kernel(const void* __restrict__ seg) {
    int n = blockIdx.x * blockDim.x + threadIdx.x;
    if (n >= NN) return;
    int m = load_seg(seg, n, g_seg_is64);
    if ((unsigned)m >= MM) return;
    int pos = atomicAdd(&g_fill[m], 1);
    g_perm[pos] = n;
}

// ---------------------------------------------------------------------------
// gather_mean: one warp per motif. Lane l accumulates s channels [8l, 8l+8);
// lanes 0-11 accumulate the 48 v floats (float4 each). No atomics, no zeroing.
// 2-node unroll for MLP.
// ---------------------------------------------------------------------------
__global__ void __launch_bounds__(256)
gather_mean_kernel(const float* __restrict__ s, const float* __restrict__ v) {
    int w = (blockIdx.x * blockDim.x + threadIdx.x) >> 5;
    if (w >= MM) return;
    int lane = threadIdx.x & 31;
    int beg = g_off[w], end = g_off[w + 1];

    float4 a0 = make_float4(0.f, 0.f, 0.f, 0.f), a1 = a0;
    float4 b0 = a0, b1 = a0;
    float4 va = a0, vb = a0;
    const float4* s4 = (const float4*)s;
    const float4* v4 = (const float4*)v;

    int i = beg;
    for (; i + 1 < end; i += 2) {
        int n0 = g_perm[i], n1 = g_perm[i + 1];
        add4(a0, s4[(size_t)n0 * 64 + lane * 2]);
        add4(b0, s4[(size_t)n1 * 64 + lane * 2]);
        add4(a1, s4[(size_t)n0 * 64 + lane * 2 + 1]);
        add4(b1, s4[(size_t)n1 * 64 + lane * 2 + 1]);
        if (lane < 12) {
            add4(va, v4[(size_t)n0 * 12 + lane]);
            add4(vb, v4[(size_t)n1 * 12 + lane]);
        }
    }
    if (i < end) {
        int n0 = g_perm[i];
        add4(a0, s4[(size_t)n0 * 64 + lane * 2]);
        add4(a1, s4[(size_t)n0 * 64 + lane * 2 + 1]);
        if (lane < 12) add4(va, v4[(size_t)n0 * 12 + lane]);
    }
    add4(a0, b0); add4(a1, b1); add4(va, vb);

    int cnt = end - beg;
    float inv = 1.0f / (float)(cnt > 0 ? cnt : 1);
    a0.x *= inv; a0.y *= inv; a0.z *= inv; a0.w *= inv;
    a1.x *= inv; a1.y *= inv; a1.z *= inv; a1.w *= inv;
    ((float4*)g_s_mean)[(size_t)w * 64 + lane * 2]     = a0;
    ((float4*)g_s_mean)[(size_t)w * 64 + lane * 2 + 1] = a1;
    if (lane < 12) {
        va.x *= inv; va.y *= inv; va.z *= inv; va.w *= inv;
        ((float4*)g_v_mean)[(size_t)w * 12 + lane] = va;
    }
}

// ---------------------------------------------------------------------------
// Single-pass tf32 mma.sync GEMM (R8 proven structure; invc removed — A is
// already the mean). BM=128, BN=128, BK=32, 8 warps 2(M)x4(N), occ=2.
// ---------------------------------------------------------------------------
#define SMO_BS   0
#define SMO_A    1024
#define SMO_B    (1024 + 16384)
#define SMO_TOTAL (1024 + 32768)

__global__ void __launch_bounds__(256, 2)
gemm_s_mma(const float* __restrict__ Ws, const float* __restrict__ bs,
           float* __restrict__ out) {
    extern __shared__ char sm[];
    uint32_t sb = smem_u32(sm);
    int tid = threadIdx.x, wid = tid >> 5, lane = tid & 31;
    int wm = wid & 1, wn = wid >> 1;
    int m0 = blockIdx.y * 128, n0 = blockIdx.x * 128;

    float* bssh = (float*)(sm + SMO_BS);
    if (tid < 128) bssh[tid] = bs[n0 + tid];
    __syncthreads();

    float acc[4][4][4];
#pragma unroll
    for (int a = 0; a < 4; a++)
#pragma unroll
        for (int b = 0; b < 4; b++)
#pragma unroll
            for (int c = 0; c < 4; c++) acc[a][b][c] = 0.f;

    int r8 = lane & 7;
    int halfA = (lane >> 3) & 1;
    int ksubA = lane >> 4;
    int ksubB = (lane >> 3) & 1;
    uint32_t aRowOff[4]; int aRsw[4];
#pragma unroll
    for (int mi = 0; mi < 4; mi++) {
        int row = wm * 64 + mi * 16 + halfA * 8 + r8;
        aRowOff[mi] = row * 128;
        aRsw[mi] = row & 7;
    }
    uint32_t bRowOff[4];
#pragma unroll
    for (int ni = 0; ni < 4; ni++)
        bRowOff[ni] = (wn * 32 + ni * 8 + r8) * 128;

    for (int ch = 0; ch < 8; ch++) {
        int kt = ch * 32;
#pragma unroll
        for (int i = 0; i < 4; i++) {
            int f = tid + 256 * i;
            int row = f >> 3, q = f & 7;
            int gm = m0 + row;
            float4 a = (gm < MM)
                ? *(const float4*)(g_s_mean + (size_t)gm * CC + kt + q * 4)
                : make_float4(0.f, 0.f, 0.f, 0.f);
            a.x = to_tf32(a.x); a.y = to_tf32(a.y);
            a.z = to_tf32(a.z); a.w = to_tf32(a.w);
            uint32_t off = row * 128 + ((q ^ (row & 7)) << 4);
            *(float4*)(sm + SMO_A + off) = a;
        }
#pragma unroll
        for (int i = 0; i < 4; i++) {
            int f = tid + 256 * i;
            int row = f >> 3, q = f & 7;
            float4 b = *(const float4*)(Ws + (size_t)(n0 + row) * CC + kt + q * 4);
            b.x = to_tf32(b.x); b.y = to_tf32(b.y);
            b.z = to_tf32(b.z); b.w = to_tf32(b.w);
            uint32_t off = row * 128 + ((q ^ (row & 7)) << 4);
            *(float4*)(sm + SMO_B + off) = b;
        }
        __syncthreads();

#pragma unroll
        for (int ks = 0; ks < 4; ks++) {
            int ks2 = ks * 2;
            uint32_t bf[4][2];
#pragma unroll
            for (int ni = 0; ni < 4; ni++)
                ldsm_x2(bf[ni], sb + SMO_B + bRowOff[ni] + (((ks2 + ksubB) ^ r8) << 4));
#pragma unroll
            for (int mi = 0; mi < 4; mi++) {
                uint32_t ah[4];
                uint32_t ca = ((uint32_t)((ks2 + ksubA) ^ aRsw[mi])) << 4;
                ldsm_x4(ah, sb + SMO_A + aRowOff[mi] + ca);
#pragma unroll
                for (int ni = 0; ni < 4; ni++)
                    mma_tf32(acc[mi][ni], ah, bf[ni]);
            }
        }
        __syncthreads();
    }

    int lr = lane >> 2, lc2 = 2 * (lane & 3);
#pragma unroll
    for (int mi = 0; mi < 4; mi++) {
#pragma unroll
        for (int ni = 0; ni < 4; ni++) {
            int lcol = wn * 32 + ni * 8 + lc2;
            float b0 = bssh[lcol], b1 = bssh[lcol + 1];
            int row0 = m0 + wm * 64 + mi * 16 + lr;
            if (row0 < MM) {
                float2 o = make_float2(acc[mi][ni][0] + b0, acc[mi][ni][1] + b1);
                *(float2*)(out + (size_t)row0 * CC + n0 + lcol) = o;
            }
            int row1 = row0 + 8;
            if (row1 < MM) {
                float2 o = make_float2(acc[mi][ni][2] + b0, acc[mi][ni][3] + b1);
                *(float2*)(out + (size_t)row1 * CC + n0 + lcol) = o;
            }
        }
    }
}

// ---------------------------------------------------------------------------
__global__ void v_out_kernel(const float* __restrict__ Wv,
                             const float* __restrict__ bv,
                             float* __restrict__ out_v) {
    int i = blockIdx.x * blockDim.x + threadIdx.x;
    if (i >= MM * VCD) return;
    int m = i / 48;
    int r = i % 48;
    int o = r / 3, d = r % 3;
    const float* vm = g_v_mean + (size_t)m * 48;
    const float* w  = Wv + o * 16;
    float sum = 0.f;
#pragma unroll
    for (int c = 0; c < 16; c++) sum += w[c] * vm[c * 3 + d];
    out_v[i] = sum + bv[o];
}

// ---------------------------------------------------------------------------
extern "C" void kernel_launch(void* const* d_in, const int* in_sizes, int n_in,
                              void* d_out, int out_size) {
    const float* s   = (const float*)d_in[0];
    const float* v   = (const float*)d_in[1];
    const void*  seg = d_in[2];
    const float* Ws  = (const float*)d_in[3];
    const float* bs  = (const float*)d_in[4];
    const float* Wv  = (const float*)d_in[5];
    const float* bv  = (const float*)d_in[6];
    float* out_s = (float*)d_out;
    float* out_v = out_s + (size_t)MM * CC;

    static int smem_set = 0;
    if (!smem_set) {
        cudaFuncSetAttribute(gemm_s_mma,
                             cudaFuncAttributeMaxDynamicSharedMemorySize, SMO_TOTAL);
        smem_set = 1;
    }

    probe_seg_kernel<<<1, 256>>>((const int*)seg);
    zero_hist_kernel<<<(MM + 255) / 256, 256>>>();
    hist_kernel<<<(NN + 255) / 256, 256>>>(seg);
    scan_a_kernel<<<NB, 256>>>();
    scan_b_kernel<<<1, 128>>>();
    scan_c_kernel<<<NB, 256>>>();
    perm_kernel<<<(NN + 255) / 256, 256>>>(seg);
    gather_mean_kernel<<<(MM * 32 + 255) / 256, 256>>>(s, v);

    dim3 gg(CC / 128, (MM + 127) / 128);
    gemm_s_mma<<<gg, 256, SMO_TOTAL>>>(Ws, bs, out_s);

    v_out_kernel<<<(MM * VCD + 255) / 256, 256>>>(Wv, bv, out_v);
}